// round 1
// baseline (speedup 1.0000x reference)
#include <cuda_runtime.h>
#include <cuda_bf16.h>

// Problem constants (fixed by the dataset)
#define BATCH  4096
#define DIN    256
#define DOUT   256
#define NEXP   64

// GEMM tiling
#define NTILE  128     // output columns per block -> 2 blocks per expert
#define MCHUNK 64      // rows per m-iteration
#define KPAD   260     // padded K stride (floats) for transposed W tile in smem
                       // (multiple of 4 for 16B-aligned float4 loads; 260%32=4
                       //  keeps the strided stores to ~4-way conflicts only)

// Dynamic shared layout (bytes):
//  s_w   : NTILE * KPAD * 4      = 133120   (W tile, transposed: s_w[c][k])
//  s_x   : MCHUNK * DIN * 4      =  65536   (x chunk, natural: s_x[r][k])
//  s_rows: BATCH * 4             =  16384   (row-index gather list)
#define SW_FLOATS   (NTILE * KPAD)
#define SX_FLOATS   (MCHUNK * DIN)
#define SMEM_BYTES  ((SW_FLOATS + SX_FLOATS) * 4 + BATCH * 4)

__device__ int g_sel[BATCH];

// ---------------------------------------------------------------------------
// Kernel 1: one-hot -> expert index
// ---------------------------------------------------------------------------
__global__ void sel_kernel(const float* __restrict__ onehot) {
    int b = blockIdx.x * blockDim.x + threadIdx.x;
    if (b >= BATCH) return;
    const float4* row = (const float4*)(onehot + (size_t)b * NEXP);
    int sel = 0;
#pragma unroll
    for (int j = 0; j < NEXP / 4; j++) {
        float4 v = row[j];
        if (v.x > 0.5f) sel = j * 4 + 0;
        if (v.y > 0.5f) sel = j * 4 + 1;
        if (v.z > 0.5f) sel = j * 4 + 2;
        if (v.w > 0.5f) sel = j * 4 + 3;
    }
    g_sel[b] = sel;
}

// packed fp32x2 FMA: d.lo += a.lo*b.lo ; d.hi += a.hi*b.hi
__device__ __forceinline__ void ffma2(unsigned long long& d,
                                      unsigned long long a,
                                      unsigned long long b) {
    asm("fma.rn.f32x2 %0, %1, %2, %0;" : "+l"(d) : "l"(a), "l"(b));
}

__device__ __forceinline__ float unpack_sum(unsigned long long a) {
    float lo = __uint_as_float((unsigned int)(a & 0xffffffffull));
    float hi = __uint_as_float((unsigned int)(a >> 32));
    return lo + hi;
}

// ---------------------------------------------------------------------------
// Kernel 2: grouped GEMM. blockIdx.y = expert, blockIdx.x = 128-col tile.
// 256 threads; thread tile = 4 rows x 8 cols, cols strided by 16 to avoid
// smem bank conflicts on the transposed-W loads.
// Accumulation is packed along K: acc.lo sums even-k, acc.hi sums odd-k.
// ---------------------------------------------------------------------------
__global__ void __launch_bounds__(256, 1)
gemm_kernel(const float* __restrict__ x,
            const float* __restrict__ W,
            const float* __restrict__ Bw,
            float* __restrict__ out) {
    extern __shared__ float smem[];
    float* s_w    = smem;                       // [NTILE][KPAD] transposed
    float* s_x    = smem + SW_FLOATS;           // [MCHUNK][DIN]
    int*   s_rows = (int*)(s_x + SX_FLOATS);    // [BATCH]
    __shared__ int s_cnt;

    const int e   = blockIdx.y;
    const int n0  = blockIdx.x * NTILE;
    const int tid = threadIdx.x;

    if (tid == 0) s_cnt = 0;
    __syncthreads();

    // --- Phase 1: gather this expert's row list (order irrelevant) ---
    for (int i = tid; i < BATCH; i += 256) {
        if (g_sel[i] == e) {
            int p = atomicAdd(&s_cnt, 1);
            s_rows[p] = i;
        }
    }

    // --- Phase 2: stage W tile transposed: s_w[c][k] = W[e][k][n0+c] ---
    {
        const float* We = W + (size_t)e * DIN * DOUT + n0;
        int k2 = tid >> 7;        // 0..1
        int o  = tid & 127;       // 0..127
        for (int k0 = 0; k0 < DIN; k0 += 2) {
            int k = k0 + k2;
            s_w[o * KPAD + k] = We[(size_t)k * DOUT + o];
        }
    }
    __syncthreads();
    const int cnt = s_cnt;

    // thread -> (rows, cols) mapping
    const int tr = tid >> 4;          // 0..15
    const int tc = tid & 15;          // 0..15
    const int r0 = tr * 4;            // rows r0..r0+3
    // cols: tc + 16*j, j = 0..7  (strided to dodge bank conflicts)

    // preload bias for my 8 columns
    float bias[8];
    {
        const float* bptr = Bw + (size_t)e * DOUT + n0;
#pragma unroll
        for (int j = 0; j < 8; j++) bias[j] = bptr[tc + 16 * j];
    }

    for (int m0 = 0; m0 < cnt; m0 += MCHUNK) {
        __syncthreads();   // previous iteration done with s_x
        const int nrows = min(MCHUNK, cnt - m0);

        // --- stage x chunk: s_x[lr][k] = x[rows[m0+lr]][k] ---
        for (int i = tid; i < MCHUNK * (DIN / 4); i += 256) {
            int lr = i >> 6;          // DIN/4 = 64 float4 per row
            int lk = i & 63;
            float4 v;
            if (lr < nrows) {
                v = ((const float4*)(x + (size_t)s_rows[m0 + lr] * DIN))[lk];
            } else {
                v = make_float4(0.f, 0.f, 0.f, 0.f);
            }
            ((float4*)s_x)[lr * 64 + lk] = v;
        }
        __syncthreads();

        // --- register-tile GEMM: 4 rows x 8 cols, K packed in f32x2 lanes ---
        unsigned long long acc[4][8];
#pragma unroll
        for (int i = 0; i < 4; i++)
#pragma unroll
            for (int j = 0; j < 8; j++) acc[i][j] = 0ull;

#pragma unroll 2
        for (int k = 0; k < DIN; k += 4) {
            // x: 4 rows, 4 consecutive k each (two packed pairs)
            ulonglong2 xv[4];
#pragma unroll
            for (int i = 0; i < 4; i++)
                xv[i] = *(const ulonglong2*)&s_x[(r0 + i) * DIN + k];
            // w: 8 cols, 4 consecutive k each
#pragma unroll
            for (int j = 0; j < 8; j++) {
                int c = tc + 16 * j;
                ulonglong2 wv = *(const ulonglong2*)&s_w[c * KPAD + k];
#pragma unroll
                for (int i = 0; i < 4; i++) {
                    ffma2(acc[i][j], xv[i].x, wv.x);
                    ffma2(acc[i][j], xv[i].y, wv.y);
                }
            }
        }

        // --- epilogue: reduce packed lanes, add bias, scatter rows ---
#pragma unroll
        for (int i = 0; i < 4; i++) {
            int m = m0 + r0 + i;
            if (m < cnt) {
                int row = s_rows[m];
                float* op = out + (size_t)row * DOUT + n0;
#pragma unroll
                for (int j = 0; j < 8; j++) {
                    op[tc + 16 * j] = unpack_sum(acc[i][j]) + bias[j];
                }
            }
        }
    }
}

// ---------------------------------------------------------------------------
extern "C" void kernel_launch(void* const* d_in, const int* in_sizes, int n_in,
                              void* d_out, int out_size) {
    const float* x      = (const float*)d_in[0];
    const float* onehot = (const float*)d_in[1];
    const float* W      = (const float*)d_in[2];
    const float* Bw     = (const float*)d_in[3];
    float* out          = (float*)d_out;

    cudaFuncSetAttribute(gemm_kernel,
                         cudaFuncAttributeMaxDynamicSharedMemorySize,
                         SMEM_BYTES);

    sel_kernel<<<BATCH / 256, 256>>>(onehot);
    gemm_kernel<<<dim3(DOUT / NTILE, NEXP), 256, SMEM_BYTES>>>(x, W, Bw, out);
}

// round 2
// speedup vs baseline: 1.2331x; 1.2331x over previous
#include <cuda_runtime.h>
#include <cuda_bf16.h>

// Problem constants
#define BATCH  4096
#define DIN    256
#define DOUT   256
#define NEXP   64

// Tiling
#define NTILE  128      // cols per block (2 blocks per expert)
#define MCHUNK 64       // rows per m-iteration
#define XSTRIDE 68      // padded stride for transposed x: bank=(4k+r)%32 -> conflict-free

// Shared layout (floats):
//  s_w : [DIN][NTILE]   natural (k-major rows, c contiguous)  = 32768 (128KB)
//  s_x : [DIN][XSTRIDE] transposed x, s_x[k][r]               = 17408 (68KB)
#define SW_FLOATS  (DIN * NTILE)
#define SX_FLOATS  (DIN * XSTRIDE)
#define SMEM_BYTES ((SW_FLOATS + SX_FLOATS) * 4)   // 200704 B

__device__ int g_cnt[NEXP];
__device__ int g_rows[NEXP * BATCH];   // per-expert gather lists

// ---------------------------------------------------------------------------
__global__ void zero_kernel() { g_cnt[threadIdx.x] = 0; }

__global__ void build_kernel(const float* __restrict__ onehot) {
    int b = blockIdx.x * blockDim.x + threadIdx.x;
    if (b >= BATCH) return;
    const float4* row = (const float4*)(onehot + (size_t)b * NEXP);
    int sel = 0;
#pragma unroll
    for (int j = 0; j < NEXP / 4; j++) {
        float4 v = row[j];
        if (v.x > 0.5f) sel = 4 * j + 0;
        if (v.y > 0.5f) sel = 4 * j + 1;
        if (v.z > 0.5f) sel = 4 * j + 2;
        if (v.w > 0.5f) sel = 4 * j + 3;
    }
    int p = atomicAdd(&g_cnt[sel], 1);
    g_rows[sel * BATCH + p] = b;
}

// packed fp32x2 FMA: d.lo += a.lo*b.lo ; d.hi += a.hi*b.hi
__device__ __forceinline__ void ffma2(unsigned long long& d,
                                      unsigned long long a,
                                      unsigned long long b) {
    asm("fma.rn.f32x2 %0, %1, %2, %0;" : "+l"(d) : "l"(a), "l"(b));
}
__device__ __forceinline__ unsigned long long dupf(float v) {
    unsigned long long r;
    asm("mov.b64 %0, {%1, %1};" : "=l"(r) : "f"(v));
    return r;
}
__device__ __forceinline__ float lo32(unsigned long long a) {
    return __uint_as_float((unsigned int)(a & 0xffffffffull));
}
__device__ __forceinline__ float hi32(unsigned long long a) {
    return __uint_as_float((unsigned int)(a >> 32));
}

// ---------------------------------------------------------------------------
// GEMM: blockIdx.y = expert, blockIdx.x = 128-col tile. 256 threads.
// Thread tile: 8 rows (4 f32x2 row-pairs) x 4 contiguous cols.
//   tc = tid & 31  -> cols c0 = 4*tc .. +3
//   tr = tid >> 5  -> rows r0 = 8*tr .. +7   (warp = one tr -> x loads broadcast)
// ---------------------------------------------------------------------------
__global__ void __launch_bounds__(256, 1)
gemm_kernel(const float* __restrict__ x,
            const float* __restrict__ W,
            const float* __restrict__ Bw,
            float* __restrict__ out) {
    extern __shared__ float smem[];
    float* s_w = smem;               // [k][c]  k*128 + c
    float* s_x = smem + SW_FLOATS;   // [k][r]  k*68 + r

    const int e   = blockIdx.y;
    const int n0  = blockIdx.x * NTILE;
    const int tid = threadIdx.x;
    const int tc  = tid & 31;
    const int tr  = tid >> 5;
    const int c0  = 4 * tc;
    const int r0  = 8 * tr;

    // --- stage W tile: float4 -> float4, no transpose, conflict-free ---
    {
        const float* We = W + ((size_t)e << 16) + n0;   // e*65536
        const int kk = tid >> 5;          // 0..7
        const int oo = (tid & 31) << 2;   // 0..124 step 4
#pragma unroll
        for (int it = 0; it < 32; it++) {
            int k = kk + (it << 3);
            float4 v = *(const float4*)(We + ((size_t)k << 8) + oo);
            *(float4*)(s_w + k * NTILE + oo) = v;
        }
    }

    const int  cnt  = g_cnt[e];
    const int* rows = g_rows + e * BATCH;

    float4 bias = *(const float4*)(Bw + (e << 8) + n0 + c0);

    for (int m0 = 0; m0 < cnt; m0 += MCHUNK) {
        __syncthreads();   // s_w ready (first iter) / previous chunk done with s_x

        // --- stage x chunk transposed: s_x[k][r] = x[rows[m0+r]][k] ---
        {
            const int r  = tid & 63;
            const int kg = tid >> 6;   // 0..3
            const int gr = m0 + r;
            const float4* xp = (gr < cnt)
                ? (const float4*)(x + ((size_t)rows[gr] << 8)) : (const float4*)0;
#pragma unroll
            for (int it = 0; it < 16; it++) {
                int k4 = kg + (it << 2);
                float4 v = xp ? xp[k4] : make_float4(0.f, 0.f, 0.f, 0.f);
                int k = k4 << 2;
                s_x[(k + 0) * XSTRIDE + r] = v.x;   // bank (4k+r)%32: conflict-free
                s_x[(k + 1) * XSTRIDE + r] = v.y;
                s_x[(k + 2) * XSTRIDE + r] = v.z;
                s_x[(k + 3) * XSTRIDE + r] = v.w;
            }
        }
        __syncthreads();

        // --- register tile: 4 row-pairs x 4 cols, f32x2-packed along rows ---
        unsigned long long acc[4][4];
#pragma unroll
        for (int p = 0; p < 4; p++)
#pragma unroll
            for (int j = 0; j < 4; j++) acc[p][j] = 0ull;

#pragma unroll 4
        for (int k = 0; k < DIN; k++) {
            // x row-pairs: rows r0..r0+7 (warp-broadcast)
            ulonglong2 aA = *(const ulonglong2*)(s_x + k * XSTRIDE + r0);
            ulonglong2 aB = *(const ulonglong2*)(s_x + k * XSTRIDE + r0 + 4);
            // W: 4 contiguous cols (32 lanes x 16B contiguous -> conflict-free)
            float4 wv = *(const float4*)(s_w + k * NTILE + c0);
            unsigned long long b0 = dupf(wv.x);
            unsigned long long b1 = dupf(wv.y);
            unsigned long long b2 = dupf(wv.z);
            unsigned long long b3 = dupf(wv.w);
            ffma2(acc[0][0], aA.x, b0); ffma2(acc[0][1], aA.x, b1);
            ffma2(acc[0][2], aA.x, b2); ffma2(acc[0][3], aA.x, b3);
            ffma2(acc[1][0], aA.y, b0); ffma2(acc[1][1], aA.y, b1);
            ffma2(acc[1][2], aA.y, b2); ffma2(acc[1][3], aA.y, b3);
            ffma2(acc[2][0], aB.x, b0); ffma2(acc[2][1], aB.x, b1);
            ffma2(acc[2][2], aB.x, b2); ffma2(acc[2][3], aB.x, b3);
            ffma2(acc[3][0], aB.y, b0); ffma2(acc[3][1], aB.y, b1);
            ffma2(acc[3][2], aB.y, b2); ffma2(acc[3][3], aB.y, b3);
        }

        // --- epilogue: unpack pairs, add bias, coalesced float4 stores ---
#pragma unroll
        for (int p = 0; p < 4; p++) {
            int m = m0 + r0 + 2 * p;
            if (m < cnt) {
                float4 v;
                v.x = lo32(acc[p][0]) + bias.x;
                v.y = lo32(acc[p][1]) + bias.y;
                v.z = lo32(acc[p][2]) + bias.z;
                v.w = lo32(acc[p][3]) + bias.w;
                *(float4*)(out + ((size_t)rows[m] << 8) + n0 + c0) = v;
            }
            if (m + 1 < cnt) {
                float4 v;
                v.x = hi32(acc[p][0]) + bias.x;
                v.y = hi32(acc[p][1]) + bias.y;
                v.z = hi32(acc[p][2]) + bias.z;
                v.w = hi32(acc[p][3]) + bias.w;
                *(float4*)(out + ((size_t)rows[m + 1] << 8) + n0 + c0) = v;
            }
        }
    }
}

// ---------------------------------------------------------------------------
extern "C" void kernel_launch(void* const* d_in, const int* in_sizes, int n_in,
                              void* d_out, int out_size) {
    const float* x      = (const float*)d_in[0];
    const float* onehot = (const float*)d_in[1];
    const float* W      = (const float*)d_in[2];
    const float* Bw     = (const float*)d_in[3];
    float* out          = (float*)d_out;

    cudaFuncSetAttribute(gemm_kernel,
                         cudaFuncAttributeMaxDynamicSharedMemorySize,
                         SMEM_BYTES);

    zero_kernel<<<1, NEXP>>>();
    build_kernel<<<BATCH / 256, 256>>>(onehot);
    gemm_kernel<<<dim3(DOUT / NTILE, NEXP), 256, SMEM_BYTES>>>(x, W, Bw, out);
}